// round 6
// baseline (speedup 1.0000x reference)
#include <cuda_runtime.h>
#include <math.h>

#define BB   256
#define SS   196
#define RNN  1024
#define ATTH 512
#define KSPLIT 8
#define KCHUNK (RNN / KSPLIT)   // 128
#define SHALF 98                 // SS/2

// Split-K partial results for att_h = h @ w_h2att^T (bias folded in later).
__device__ float g_atth_part[KSPLIT * BB * ATTH];   // 4 MB
// Raw (pre-softmax) scores.
__device__ float g_scores[BB * SS];                 // 200 KB

// ---------------------------------------------------------------------------
// Kernel 1: split-K tiled fp32 GEMM: att_h_part[z][m][n] = h[m,kz]·w[n,kz]
// Grid: (8, 4, 8) = 256 blocks, 256 threads.
// ---------------------------------------------------------------------------
__global__ __launch_bounds__(256) void gemm_atth_kernel(
    const float* __restrict__ h, const float* __restrict__ w) {
  const int n0 = blockIdx.x * 64;
  const int m0 = blockIdx.y * 64;
  const int k0 = blockIdx.z * KCHUNK;

  __shared__ float As[16][65];
  __shared__ float Bs[16][65];

  const int t    = threadIdx.x;
  const int lrow = t >> 2;
  const int lk4  = (t & 3) * 4;
  const int tx   = (t & 15) * 4;
  const int ty   = (t >> 4) * 4;

  float acc[4][4] = {};

  for (int kk = 0; kk < KCHUNK; kk += 16) {
    const float4 av = *(const float4*)(h + (size_t)(m0 + lrow) * RNN + k0 + kk + lk4);
    const float4 bv = *(const float4*)(w + (size_t)(n0 + lrow) * RNN + k0 + kk + lk4);
    __syncthreads();
    As[lk4 + 0][lrow] = av.x; As[lk4 + 1][lrow] = av.y;
    As[lk4 + 2][lrow] = av.z; As[lk4 + 3][lrow] = av.w;
    Bs[lk4 + 0][lrow] = bv.x; Bs[lk4 + 1][lrow] = bv.y;
    Bs[lk4 + 2][lrow] = bv.z; Bs[lk4 + 3][lrow] = bv.w;
    __syncthreads();
#pragma unroll
    for (int k = 0; k < 16; k++) {
      float a[4], b[4];
#pragma unroll
      for (int i = 0; i < 4; i++) a[i] = As[k][ty + i];
#pragma unroll
      for (int j = 0; j < 4; j++) b[j] = Bs[k][tx + j];
#pragma unroll
      for (int i = 0; i < 4; i++)
#pragma unroll
        for (int j = 0; j < 4; j++)
          acc[i][j] = fmaf(a[i], b[j], acc[i][j]);
    }
  }

  float* dst = g_atth_part + (size_t)blockIdx.z * BB * ATTH;
#pragma unroll
  for (int i = 0; i < 4; i++)
#pragma unroll
    for (int j = 0; j < 4; j++)
      dst[(size_t)(m0 + ty + i) * ATTH + (n0 + tx + j)] = acc[i][j];
}

// ---------------------------------------------------------------------------
// Kernel 2: raw scores.
//   scores[b,s] = sum_a tanh(p_att[b,s,a] + att_h[b,a] + bias[a]) * w_alpha[a]
// Grid: (BB, 2), 256 threads. Block (b,g) handles s in [g*98, (g+1)*98).
// ---------------------------------------------------------------------------
__global__ __launch_bounds__(256) void scores_kernel(
    const float* __restrict__ p_att,
    const float* __restrict__ b_h2att,
    const float* __restrict__ w_alpha) {
  __shared__ __align__(16) float sh_atth[ATTH];
  __shared__ __align__(16) float sh_wa[ATTH];

  const int b    = blockIdx.x;
  const int g    = blockIdx.y;
  const int tid  = threadIdx.x;
  const int warp = tid >> 5;
  const int lane = tid & 31;

  // Sum split-K partials + bias into shared att_h; stage w_alpha.
#pragma unroll
  for (int a = tid; a < ATTH; a += 256) {
    float v = b_h2att[a];
#pragma unroll
    for (int z = 0; z < KSPLIT; z++)
      v += g_atth_part[(size_t)z * BB * ATTH + (size_t)b * ATTH + a];
    sh_atth[a] = v;
    sh_wa[a] = w_alpha[a];
  }
  __syncthreads();

  const float* pbase = p_att + (size_t)b * SS * ATTH + (size_t)g * SHALF * ATTH;
  for (int sl = warp; sl < SHALF; sl += 8) {
    const float* row = pbase + (size_t)sl * ATTH;
    float acc = 0.f;
#pragma unroll
    for (int i = 0; i < 4; i++) {
      const int a = i * 128 + lane * 4;
      const float4 p  = *(const float4*)(row + a);
      const float4 ah = *(const float4*)(sh_atth + a);
      const float4 wa = *(const float4*)(sh_wa + a);
      acc += tanhf(p.x + ah.x) * wa.x;
      acc += tanhf(p.y + ah.y) * wa.y;
      acc += tanhf(p.z + ah.z) * wa.z;
      acc += tanhf(p.w + ah.w) * wa.w;
    }
#pragma unroll
    for (int off = 16; off > 0; off >>= 1)
      acc += __shfl_xor_sync(0xffffffffu, acc, off);
    if (lane == 0) g_scores[(size_t)b * SS + g * SHALF + sl] = acc;
  }
}

// ---------------------------------------------------------------------------
// Kernel 3: redundant softmax prologue + weighted sum.
//   out[b, g*512 + t*4 .. +3] = sum_s softmax(scores[b])[s] * att_feats[b,s,·]
// Grid: (BB, 2), 128 threads, float4 per thread (128*4 = 512 dims per block).
// ---------------------------------------------------------------------------
__global__ __launch_bounds__(128) void wsum_kernel(
    const float* __restrict__ att_feats,
    float* __restrict__ out) {
  __shared__ float sh_w[SS];
  __shared__ float red[4];

  const int b    = blockIdx.x;
  const int g    = blockIdx.y;
  const int tid  = threadIdx.x;      // 0..127
  const int warp = tid >> 5;
  const int lane = tid & 31;

  // --- softmax over 196 scores (each thread holds up to 2) ---
  const float* sc = g_scores + (size_t)b * SS;
  const float v1 = sc[tid];                                    // tid < 196 always
  const float v2 = (tid + 128 < SS) ? sc[tid + 128] : -INFINITY;

  float m = fmaxf(v1, v2);
#pragma unroll
  for (int off = 16; off > 0; off >>= 1)
    m = fmaxf(m, __shfl_xor_sync(0xffffffffu, m, off));
  if (lane == 0) red[warp] = m;
  __syncthreads();
  m = fmaxf(fmaxf(red[0], red[1]), fmaxf(red[2], red[3]));
  __syncthreads();

  const float e1 = expf(v1 - m);
  const float e2 = (tid + 128 < SS) ? expf(v2 - m) : 0.f;
  float sum = e1 + e2;
#pragma unroll
  for (int off = 16; off > 0; off >>= 1)
    sum += __shfl_xor_sync(0xffffffffu, sum, off);
  if (lane == 0) red[warp] = sum;
  __syncthreads();
  const float inv = 1.f / (red[0] + red[1] + red[2] + red[3]);

  sh_w[tid] = e1 * inv;
  if (tid + 128 < SS) sh_w[tid + 128] = e2 * inv;
  __syncthreads();

  // --- stream att_feats chunk: 196 x float4 per thread ---
  const float* abase = att_feats + (size_t)b * SS * RNN + (size_t)g * 512 + (size_t)tid * 4;
  float4 acc = make_float4(0.f, 0.f, 0.f, 0.f);
#pragma unroll 4
  for (int s = 0; s < SS; s++) {
    const float ws = sh_w[s];
    const float4 v = *(const float4*)(abase + (size_t)s * RNN);
    acc.x = fmaf(ws, v.x, acc.x);
    acc.y = fmaf(ws, v.y, acc.y);
    acc.z = fmaf(ws, v.z, acc.z);
    acc.w = fmaf(ws, v.w, acc.w);
  }
  *(float4*)(out + (size_t)b * RNN + (size_t)g * 512 + (size_t)tid * 4) = acc;
}

// ---------------------------------------------------------------------------
// Launch. Inputs: h, att_feats, p_att_feats, w_h2att, b_h2att, w_alpha,
// b_alpha (unused: softmax shift-invariant).
// ---------------------------------------------------------------------------
extern "C" void kernel_launch(void* const* d_in, const int* in_sizes, int n_in,
                              void* d_out, int out_size) {
  (void)in_sizes; (void)n_in; (void)out_size;
  const float* h         = (const float*)d_in[0];
  const float* att_feats = (const float*)d_in[1];
  const float* p_att     = (const float*)d_in[2];
  const float* w_h2att   = (const float*)d_in[3];
  const float* b_h2att   = (const float*)d_in[4];
  const float* w_alpha   = (const float*)d_in[5];
  float* out = (float*)d_out;

  dim3 g1(ATTH / 64, BB / 64, KSPLIT);   // 256 blocks
  gemm_atth_kernel<<<g1, 256>>>(h, w_h2att);
  scores_kernel<<<dim3(BB, 2), 256>>>(p_att, b_h2att, w_alpha);
  wsum_kernel<<<dim3(BB, 2), 128>>>(att_feats, out);
}

// round 7
// speedup vs baseline: 1.1234x; 1.1234x over previous
#include <cuda_runtime.h>
#include <math.h>

#define BB   256
#define SS   196
#define RNN  1024
#define ATTH 512
#define KSPLIT 8
#define KCHUNK (RNN / KSPLIT)   // 128

// Split-K partial results for att_h = h @ w_h2att^T (bias folded in later).
__device__ float g_atth_part[KSPLIT * BB * ATTH];   // 4 MB

// Fast accurate tanh: tanh(x) = 1 - 2/(exp(2x)+1); ex2/rcp MUFU, ~1e-7 abs err.
__device__ __forceinline__ float fast_tanhf(float x) {
  float e;
  asm("ex2.approx.f32 %0, %1;" : "=f"(e) : "f"(x * 2.885390081777927f)); // 2*log2(e)
  float r;
  asm("rcp.approx.f32 %0, %1;" : "=f"(r) : "f"(e + 1.0f));
  return fmaf(-2.0f, r, 1.0f);
}

// ---------------------------------------------------------------------------
// Kernel 1: split-K tiled fp32 GEMM, 32x32 output tiles.
//   att_h_part[z][m][n] = sum_{k in chunk z} h[m][k] * w[n][k]
// Grid: (ATTH/32, BB/32, KSPLIT) = (16, 8, 8) = 1024 blocks, 256 threads.
// ---------------------------------------------------------------------------
__global__ __launch_bounds__(256) void gemm_atth_kernel(
    const float* __restrict__ h, const float* __restrict__ w) {
  const int n0 = blockIdx.x * 32;
  const int m0 = blockIdx.y * 32;
  const int k0 = blockIdx.z * KCHUNK;

  __shared__ float As[16][33];
  __shared__ float Bs[16][33];

  const int t    = threadIdx.x;            // 0..255
  const int lrow = (t & 127) >> 2;         // 0..31
  const int lk4  = (t & 3) * 4;            // 0,4,8,12
  const bool isB = (t >= 128);
  const float* src = isB ? (w + (size_t)(n0 + lrow) * RNN)
                         : (h + (size_t)(m0 + lrow) * RNN);
  const int tx = (t & 15) * 2;             // n micro
  const int ty = (t >> 4) * 2;             // m micro

  float a00 = 0.f, a01 = 0.f, a10 = 0.f, a11 = 0.f;

  for (int kk = 0; kk < KCHUNK; kk += 16) {
    const float4 v = *(const float4*)(src + k0 + kk + lk4);
    __syncthreads();
    float (*S)[33] = isB ? Bs : As;
    S[lk4 + 0][lrow] = v.x; S[lk4 + 1][lrow] = v.y;
    S[lk4 + 2][lrow] = v.z; S[lk4 + 3][lrow] = v.w;
    __syncthreads();
#pragma unroll
    for (int k = 0; k < 16; k++) {
      const float av0 = As[k][ty], av1 = As[k][ty + 1];
      const float bv0 = Bs[k][tx], bv1 = Bs[k][tx + 1];
      a00 = fmaf(av0, bv0, a00); a01 = fmaf(av0, bv1, a01);
      a10 = fmaf(av1, bv0, a10); a11 = fmaf(av1, bv1, a11);
    }
  }

  float* dst = g_atth_part + (size_t)blockIdx.z * BB * ATTH;
  *(float2*)(dst + (size_t)(m0 + ty + 0) * ATTH + n0 + tx) = make_float2(a00, a01);
  *(float2*)(dst + (size_t)(m0 + ty + 1) * ATTH + n0 + tx) = make_float2(a10, a11);
}

// ---------------------------------------------------------------------------
// Kernel 2: fused per-batch attention (R4 structure + fast tanh + float4 B).
// Grid: 256 blocks, 512 threads.
// ---------------------------------------------------------------------------
__global__ __launch_bounds__(512) void attn_fused_kernel(
    const float* __restrict__ att_feats,
    const float* __restrict__ p_att,
    const float* __restrict__ b_h2att,
    const float* __restrict__ w_alpha,
    float* __restrict__ out) {
  __shared__ __align__(16) float sh_atth[ATTH];
  __shared__ __align__(16) float sh_wa[ATTH];
  __shared__ __align__(16) float sh_part[RNN];
  __shared__ float sh_sc[SS];

  const int b    = blockIdx.x;
  const int tid  = threadIdx.x;
  const int warp = tid >> 5;
  const int lane = tid & 31;

  // Prologue: sum split-K partials + bias into shared att_h; stage w_alpha.
  {
    float v = b_h2att[tid];
#pragma unroll
    for (int z = 0; z < KSPLIT; z++)
      v += g_atth_part[(size_t)z * BB * ATTH + (size_t)b * ATTH + tid];
    sh_atth[tid] = v;
    sh_wa[tid] = w_alpha[tid];
  }
  __syncthreads();

  // ---- Phase A: scores (one warp per s-row, strided) ----
  const float* pbase = p_att + (size_t)b * SS * ATTH;
  for (int s = warp; s < SS; s += 16) {
    const float* row = pbase + (size_t)s * ATTH;
    float acc = 0.f;
#pragma unroll
    for (int i = 0; i < 4; i++) {
      const int a = i * 128 + lane * 4;
      const float4 p  = *(const float4*)(row + a);
      const float4 ah = *(const float4*)(sh_atth + a);
      const float4 wa = *(const float4*)(sh_wa + a);
      acc = fmaf(fast_tanhf(p.x + ah.x), wa.x, acc);
      acc = fmaf(fast_tanhf(p.y + ah.y), wa.y, acc);
      acc = fmaf(fast_tanhf(p.z + ah.z), wa.z, acc);
      acc = fmaf(fast_tanhf(p.w + ah.w), wa.w, acc);
    }
#pragma unroll
    for (int off = 16; off > 0; off >>= 1)
      acc += __shfl_xor_sync(0xffffffffu, acc, off);
    if (lane == 0) sh_sc[s] = acc;
  }
  __syncthreads();

  // ---- Softmax over S (warp 0) ----
  if (warp == 0) {
    float m = -INFINITY;
    for (int s = lane; s < SS; s += 32) m = fmaxf(m, sh_sc[s]);
#pragma unroll
    for (int off = 16; off > 0; off >>= 1)
      m = fmaxf(m, __shfl_xor_sync(0xffffffffu, m, off));
    float sum = 0.f;
    for (int s = lane; s < SS; s += 32) {
      const float e = __expf(sh_sc[s] - m);
      sh_sc[s] = e;
      sum += e;
    }
#pragma unroll
    for (int off = 16; off > 0; off >>= 1)
      sum += __shfl_xor_sync(0xffffffffu, sum, off);
    const float inv = 1.f / sum;
    for (int s = lane; s < SS; s += 32) sh_sc[s] *= inv;
  }
  __syncthreads();

  // ---- Phase B: weighted sum, s-range split across thread halves, float4 ----
  // Half 0 (tid 0..255): s in [0,98), dims tid*4..tid*4+3
  // Half 1 (tid 256..511): s in [98,196), same dims; combine via smem.
  const int half = tid >> 8;           // 0 or 1
  const int dt   = tid & 255;          // 0..255 -> dim = dt*4
  const int s0   = half * 98;
  const float* abase = att_feats + (size_t)b * SS * RNN + (size_t)s0 * RNN + (size_t)dt * 4;

  float4 acc = make_float4(0.f, 0.f, 0.f, 0.f);
#pragma unroll 7
  for (int s = 0; s < 98; s++) {
    const float ws = sh_sc[s0 + s];
    const float4 v = *(const float4*)(abase + (size_t)s * RNN);
    acc.x = fmaf(ws, v.x, acc.x);
    acc.y = fmaf(ws, v.y, acc.y);
    acc.z = fmaf(ws, v.z, acc.z);
    acc.w = fmaf(ws, v.w, acc.w);
  }

  if (half == 0) {
    *(float4*)(sh_part + dt * 4) = acc;
  }
  __syncthreads();
  if (half == 1) {
    const float4 p = *(const float4*)(sh_part + dt * 4);
    acc.x += p.x; acc.y += p.y; acc.z += p.z; acc.w += p.w;
    *(float4*)(out + (size_t)b * RNN + (size_t)dt * 4) = acc;
  }
}

// ---------------------------------------------------------------------------
// Launch. Inputs: h, att_feats, p_att_feats, w_h2att, b_h2att, w_alpha,
// b_alpha (unused: softmax shift-invariant).
// ---------------------------------------------------------------------------
extern "C" void kernel_launch(void* const* d_in, const int* in_sizes, int n_in,
                              void* d_out, int out_size) {
  (void)in_sizes; (void)n_in; (void)out_size;
  const float* h         = (const float*)d_in[0];
  const float* att_feats = (const float*)d_in[1];
  const float* p_att     = (const float*)d_in[2];
  const float* w_h2att   = (const float*)d_in[3];
  const float* b_h2att   = (const float*)d_in[4];
  const float* w_alpha   = (const float*)d_in[5];
  float* out = (float*)d_out;

  dim3 g1(ATTH / 32, BB / 32, KSPLIT);   // 1024 blocks
  gemm_atth_kernel<<<g1, 256>>>(h, w_h2att);
  attn_fused_kernel<<<BB, 512>>>(att_feats, p_att, b_h2att, w_alpha, out);
}

// round 8
// speedup vs baseline: 1.2330x; 1.0976x over previous
#include <cuda_runtime.h>
#include <math.h>

#define BB   256
#define SS   196
#define RNN  1024
#define ATTH 512
#define KSPLIT 8
#define KCHUNK 128   // RNN / KSPLIT
#define SQ   49      // SS / 4

// Split-K partials for att_h = h @ w_h2att^T (bias folded in later).
__device__ float g_atth_part[KSPLIT * BB * ATTH];   // 4 MB
// Raw (pre-softmax) scores.
__device__ float g_scores[BB * SS];                 // 200 KB

// Fast accurate tanh: tanh(x) = 1 - 2/(exp(2x)+1); 2 MUFU, ~1e-7 abs err.
__device__ __forceinline__ float fast_tanhf(float x) {
  float e;
  asm("ex2.approx.f32 %0, %1;" : "=f"(e) : "f"(x * 2.885390081777927f));
  float r;
  asm("rcp.approx.f32 %0, %1;" : "=f"(r) : "f"(e + 1.0f));
  return fmaf(-2.0f, r, 1.0f);
}

// ---------------------------------------------------------------------------
// Kernel 1: split-K GEMM, 32x32x128 tiles, single-stage smem, f32x2 FMA.
//   att_h_part[z][m][n] = sum_{k in chunk z} h[m][k] * w[n][k]
// Grid: (16, 8, 8) = 1024 blocks, 256 threads.
// ---------------------------------------------------------------------------
__global__ __launch_bounds__(256) void gemm_atth_kernel(
    const float* __restrict__ h, const float* __restrict__ w) {
  const int n0 = blockIdx.x * 32;
  const int m0 = blockIdx.y * 32;
  const int k0 = blockIdx.z * KCHUNK;

  // [k][m] layout, pad 34 keeps float2/u64 reads 8B-aligned (even stride).
  __shared__ float As[KCHUNK][34];
  __shared__ float Bs[KCHUNK][34];

  const int t  = threadIdx.x;          // 0..255
  const int r  = t >> 3;               // 0..31 (tile row)
  const int cb = (t & 7) * 4;          // k sub-offset

  // Load full A and B tiles (transposed into [k][m]); batched LDG.128s.
#pragma unroll
  for (int i = 0; i < 4; i++) {
    const int c = cb + i * 32;
    const float4 v = *(const float4*)(h + (size_t)(m0 + r) * RNN + k0 + c);
    As[c + 0][r] = v.x; As[c + 1][r] = v.y; As[c + 2][r] = v.z; As[c + 3][r] = v.w;
  }
#pragma unroll
  for (int i = 0; i < 4; i++) {
    const int c = cb + i * 32;
    const float4 v = *(const float4*)(w + (size_t)(n0 + r) * RNN + k0 + c);
    Bs[c + 0][r] = v.x; Bs[c + 1][r] = v.y; Bs[c + 2][r] = v.z; Bs[c + 3][r] = v.w;
  }
  __syncthreads();

  const int tx = (t & 15) * 2;         // n micro (2 cols)
  const int ty = (t >> 4) * 2;         // m micro (2 rows)

  // acc0 = (d[ty][tx],   d[ty+1][tx])   packed f32x2
  // acc1 = (d[ty][tx+1], d[ty+1][tx+1]) packed f32x2
  unsigned long long acc0 = 0ull, acc1 = 0ull;

#pragma unroll 16
  for (int k = 0; k < KCHUNK; k++) {
    const unsigned long long a2 = *(const unsigned long long*)&As[k][ty];
    const float2 b2 = *(const float2*)&Bs[k][tx];
    unsigned long long bb0, bb1;
    asm("mov.b64 %0, {%1, %1};" : "=l"(bb0) : "r"(__float_as_uint(b2.x)));
    asm("mov.b64 %0, {%1, %1};" : "=l"(bb1) : "r"(__float_as_uint(b2.y)));
    asm("fma.rn.f32x2 %0, %1, %2, %0;" : "+l"(acc0) : "l"(a2), "l"(bb0));
    asm("fma.rn.f32x2 %0, %1, %2, %0;" : "+l"(acc1) : "l"(a2), "l"(bb1));
  }

  const float lo0 = __uint_as_float((unsigned)acc0);
  const float hi0 = __uint_as_float((unsigned)(acc0 >> 32));
  const float lo1 = __uint_as_float((unsigned)acc1);
  const float hi1 = __uint_as_float((unsigned)(acc1 >> 32));

  float* dst = g_atth_part + (size_t)blockIdx.z * BB * ATTH;
  *(float2*)(dst + (size_t)(m0 + ty + 0) * ATTH + n0 + tx) = make_float2(lo0, lo1);
  *(float2*)(dst + (size_t)(m0 + ty + 1) * ATTH + n0 + tx) = make_float2(hi0, hi1);
}

// ---------------------------------------------------------------------------
// Kernel 2: raw scores.
//   scores[b,s] = sum_a tanh(p_att[b,s,a] + att_h[b,a] + bias[a]) * w_alpha[a]
// Grid: (BB, 4) = 1024 blocks, 256 threads. Block (b,q) handles 49 s-rows.
// ---------------------------------------------------------------------------
__global__ __launch_bounds__(256) void scores_kernel(
    const float* __restrict__ p_att,
    const float* __restrict__ b_h2att,
    const float* __restrict__ w_alpha) {
  __shared__ __align__(16) float sh_atth[ATTH];
  __shared__ __align__(16) float sh_wa[ATTH];

  const int b    = blockIdx.x;
  const int q    = blockIdx.y;
  const int tid  = threadIdx.x;
  const int warp = tid >> 5;
  const int lane = tid & 31;

#pragma unroll
  for (int a = tid; a < ATTH; a += 256) {
    float v = b_h2att[a];
#pragma unroll
    for (int z = 0; z < KSPLIT; z++)
      v += g_atth_part[(size_t)z * BB * ATTH + (size_t)b * ATTH + a];
    sh_atth[a] = v;
    sh_wa[a] = w_alpha[a];
  }
  __syncthreads();

  const float* pbase = p_att + (size_t)b * SS * ATTH + (size_t)q * SQ * ATTH;
  for (int sl = warp; sl < SQ; sl += 8) {
    const float* row = pbase + (size_t)sl * ATTH;
    float acc = 0.f;
#pragma unroll
    for (int i = 0; i < 4; i++) {
      const int a = i * 128 + lane * 4;
      const float4 p  = *(const float4*)(row + a);
      const float4 ah = *(const float4*)(sh_atth + a);
      const float4 wa = *(const float4*)(sh_wa + a);
      acc = fmaf(fast_tanhf(p.x + ah.x), wa.x, acc);
      acc = fmaf(fast_tanhf(p.y + ah.y), wa.y, acc);
      acc = fmaf(fast_tanhf(p.z + ah.z), wa.z, acc);
      acc = fmaf(fast_tanhf(p.w + ah.w), wa.w, acc);
    }
#pragma unroll
    for (int off = 16; off > 0; off >>= 1)
      acc += __shfl_xor_sync(0xffffffffu, acc, off);
    if (lane == 0) g_scores[(size_t)b * SS + q * SQ + sl] = acc;
  }
}

// ---------------------------------------------------------------------------
// Kernel 3: redundant softmax prologue + weighted sum, direct store.
//   out[b, q*256+t] = sum_s softmax(scores[b])[s] * att_feats[b,s,q*256+t]
// Grid: (BB, 4) = 1024 blocks, 256 threads, 1 output dim per thread.
// ---------------------------------------------------------------------------
__global__ __launch_bounds__(256) void wsum_kernel(
    const float* __restrict__ att_feats,
    float* __restrict__ out) {
  __shared__ float sh_w[SS];
  __shared__ float red[8];

  const int b    = blockIdx.x;
  const int q    = blockIdx.y;
  const int tid  = threadIdx.x;
  const int warp = tid >> 5;
  const int lane = tid & 31;

  // --- softmax over 196 scores ---
  const float v = (tid < SS) ? g_scores[(size_t)b * SS + tid] : -INFINITY;

  float m = v;
#pragma unroll
  for (int off = 16; off > 0; off >>= 1)
    m = fmaxf(m, __shfl_xor_sync(0xffffffffu, m, off));
  if (lane == 0) red[warp] = m;
  __syncthreads();
  m = red[0];
#pragma unroll
  for (int i = 1; i < 8; i++) m = fmaxf(m, red[i]);
  __syncthreads();

  const float e = (tid < SS) ? __expf(v - m) : 0.f;
  float sum = e;
#pragma unroll
  for (int off = 16; off > 0; off >>= 1)
    sum += __shfl_xor_sync(0xffffffffu, sum, off);
  if (lane == 0) red[warp] = sum;
  __syncthreads();
  float tot = red[0];
#pragma unroll
  for (int i = 1; i < 8; i++) tot += red[i];
  const float inv = 1.f / tot;
  if (tid < SS) sh_w[tid] = e * inv;
  __syncthreads();

  // --- stream att_feats: 196 coalesced scalar loads per thread ---
  const int d = q * 256 + tid;
  const float* ab = att_feats + (size_t)b * SS * RNN + d;
  float acc = 0.f;
#pragma unroll 4
  for (int s = 0; s < SS; s++)
    acc = fmaf(sh_w[s], ab[(size_t)s * RNN], acc);

  out[(size_t)b * RNN + d] = acc;
}

// ---------------------------------------------------------------------------
// Launch. Inputs: h, att_feats, p_att_feats, w_h2att, b_h2att, w_alpha,
// b_alpha (unused: softmax shift-invariant).
// ---------------------------------------------------------------------------
extern "C" void kernel_launch(void* const* d_in, const int* in_sizes, int n_in,
                              void* d_out, int out_size) {
  (void)in_sizes; (void)n_in; (void)out_size;
  const float* h         = (const float*)d_in[0];
  const float* att_feats = (const float*)d_in[1];
  const float* p_att     = (const float*)d_in[2];
  const float* w_h2att   = (const float*)d_in[3];
  const float* b_h2att   = (const float*)d_in[4];
  const float* w_alpha   = (const float*)d_in[5];
  float* out = (float*)d_out;

  dim3 g1(ATTH / 32, BB / 32, KSPLIT);      // 1024 blocks
  gemm_atth_kernel<<<g1, 256>>>(h, w_h2att);
  scores_kernel<<<dim3(BB, 4), 256>>>(p_att, b_h2att, w_alpha);
  wsum_kernel<<<dim3(BB, 4), 256>>>(att_feats, out);
}